// round 2
// baseline (speedup 1.0000x reference)
#include <cuda_runtime.h>

// out[b, t, h] = sum_{j=0..4} x[b, t+j, h] * a[b, t+j]
// x: (32, 1, 2052, 768) f32, a: (32, 2052) f32, out: (32, 1, 2048, 768) f32
//
// HBM-bound streaming kernel. Register sliding window of 5 pre-weighted rows.
// R2 change: TT 128 -> 64 (2x CTAs => ~41 warps/SM instead of ~20) and
// unroll 8 for deeper per-thread MLP; __ldcs streaming loads for x.

constexpr int LENGTH = 2048;
constexpr int WIDTH  = 5;
constexpr int H      = 768;
constexpr int PAD    = LENGTH + WIDTH - 1;   // 2052
constexpr int H4     = H / 4;                // 192
constexpr int TT     = 64;                   // t-positions per CTA
constexpr int B      = 32;

__device__ __forceinline__ float4 ldcs4(const float4* p) {
    return __ldcs(p);
}

__global__ __launch_bounds__(H4) void widthap_kernel(
    const float* __restrict__ x,
    const float* __restrict__ att,
    float* __restrict__ out)
{
    const int b  = blockIdx.y;
    const int t0 = blockIdx.x * TT;
    const int h4 = threadIdx.x;          // 0..191

    __shared__ float sa[TT + WIDTH - 1]; // weights for rows t0 .. t0+TT+3

    if (threadIdx.x < TT + WIDTH - 1)
        sa[threadIdx.x] = att[b * PAD + t0 + threadIdx.x];
    __syncthreads();

    const float4* __restrict__ xb =
        reinterpret_cast<const float4*>(x + (size_t)b * PAD * H) + h4;
    float4* __restrict__ ob =
        reinterpret_cast<float4*>(out + (size_t)b * LENGTH * H) + h4;

    // Prologue: load+weight first 4 rows of the window.
    float4 w0, w1, w2, w3;
    {
        float4 v;
        float a;
        v = ldcs4(xb + (size_t)(t0 + 0) * H4); a = sa[0];
        w0 = make_float4(v.x * a, v.y * a, v.z * a, v.w * a);
        v = ldcs4(xb + (size_t)(t0 + 1) * H4); a = sa[1];
        w1 = make_float4(v.x * a, v.y * a, v.z * a, v.w * a);
        v = ldcs4(xb + (size_t)(t0 + 2) * H4); a = sa[2];
        w2 = make_float4(v.x * a, v.y * a, v.z * a, v.w * a);
        v = ldcs4(xb + (size_t)(t0 + 3) * H4); a = sa[3];
        w3 = make_float4(v.x * a, v.y * a, v.z * a, v.w * a);
    }

    #pragma unroll 8
    for (int i = 0; i < TT; i++) {
        float4 v = ldcs4(xb + (size_t)(t0 + i + 4) * H4);
        float  a = sa[i + 4];
        float4 w4 = make_float4(v.x * a, v.y * a, v.z * a, v.w * a);

        float4 s;
        s.x = w0.x + w1.x + w2.x + w3.x + w4.x;
        s.y = w0.y + w1.y + w2.y + w3.y + w4.y;
        s.z = w0.z + w1.z + w2.z + w3.z + w4.z;
        s.w = w0.w + w1.w + w2.w + w3.w + w4.w;

        ob[(size_t)(t0 + i) * H4] = s;

        w0 = w1; w1 = w2; w2 = w3; w3 = w4;
    }
}

extern "C" void kernel_launch(void* const* d_in, const int* in_sizes, int n_in,
                              void* d_out, int out_size)
{
    const float* x   = (const float*)d_in[0];       // (32,1,2052,768)
    const float* att = (const float*)d_in[1];       // (32,2052)
    float* out       = (float*)d_out;               // (32,1,2048,768)

    dim3 grid(LENGTH / TT, B);   // (32, 32) = 1024 CTAs
    dim3 block(H4);              // 192 threads
    widthap_kernel<<<grid, block>>>(x, att, out);
}

// round 3
// speedup vs baseline: 1.4589x; 1.4589x over previous
#include <cuda_runtime.h>
#include <cstdint>

// out[b, t, h] = sum_{j=0..4} x[b, t+j, h] * a[b, t+j]
// x: (32,1,2052,768) f32, a: (32,2052) f32, out: (32,1,2048,768) f32
//
// R3: cp.async.bulk staging pipeline.
//   - Each CTA owns (b, 64 output rows). Input rows stream g->smem in 24KB
//     chunks (8 rows) through a 4-stage mbarrier ring (bulk async, bypasses
//     L1tex MSHR limits, gives the MC large contiguous bursts).
//   - 384 threads compute the width-5 weighted window sum from smem into a
//     2-stage smem output ring; 24KB bulk stores smem->global.

constexpr int LENGTH = 2048;
constexpr int WIDTH  = 5;
constexpr int H      = 768;
constexpr int PAD    = LENGTH + WIDTH - 1;   // 2052
constexpr int ROWB   = H * 4;                // 3072 bytes per row
constexpr int TT     = 64;                   // output rows per CTA
constexpr int CR     = 8;                    // rows per chunk
constexpr int CHUNK  = CR * ROWB;            // 24576 bytes
constexpr int NCH    = TT / CR;              // 8 output chunks
constexpr int NIN    = NCH + 1;              // 9 input chunks (last is 4 rows)
constexpr int IN_STAGES  = 4;
constexpr int OUT_STAGES = 2;
constexpr int B      = 32;
constexpr int THREADS = 384;

// dynamic smem layout (bytes)
constexpr int MBAR_OFF = 0;                         // 4 mbarriers * 8B
constexpr int WA_OFF   = 64;                        // 68 floats
constexpr int IN_OFF   = 512;
constexpr int OUT_OFF  = IN_OFF + IN_STAGES * CHUNK;      // 98816
constexpr int SMEM_TOTAL = OUT_OFF + OUT_STAGES * CHUNK;  // 147968

__device__ __forceinline__ uint32_t smem_u32(const void* p) {
    return (uint32_t)__cvta_generic_to_shared(p);
}

__device__ __forceinline__ void mbar_init(uint32_t bar, uint32_t count) {
    asm volatile("mbarrier.init.shared.b64 [%0], %1;" :: "r"(bar), "r"(count) : "memory");
}

__device__ __forceinline__ void mbar_expect_tx(uint32_t bar, uint32_t bytes) {
    asm volatile("mbarrier.arrive.expect_tx.shared.b64 _, [%0], %1;"
                 :: "r"(bar), "r"(bytes) : "memory");
}

__device__ __forceinline__ void mbar_wait(uint32_t bar, uint32_t parity) {
    uint32_t done;
    asm volatile(
        "{\n\t.reg .pred p;\n\t"
        "mbarrier.try_wait.parity.acquire.cta.shared::cta.b64 p, [%1], %2;\n\t"
        "selp.b32 %0, 1, 0, p;\n\t}"
        : "=r"(done) : "r"(bar), "r"(parity) : "memory");
    if (!done) {
        asm volatile(
            "{\n\t.reg .pred P1;\n\t"
            "W_%=:\n\t"
            "mbarrier.try_wait.parity.acquire.cta.shared::cta.b64 P1, [%0], %1, 0x989680;\n\t"
            "@P1 bra.uni D_%=;\n\t"
            "bra.uni W_%=;\n\t"
            "D_%=:\n\t}"
            :: "r"(bar), "r"(parity) : "memory");
    }
}

__device__ __forceinline__ void bulk_g2s(uint32_t dst_smem, const void* src_gmem,
                                         uint32_t bytes, uint32_t bar) {
    asm volatile(
        "cp.async.bulk.shared::cluster.global.mbarrier::complete_tx::bytes "
        "[%0], [%1], %2, [%3];"
        :: "r"(dst_smem), "l"(src_gmem), "r"(bytes), "r"(bar) : "memory");
}

__device__ __forceinline__ void bulk_s2g(void* dst_gmem, uint32_t src_smem,
                                         uint32_t bytes) {
    asm volatile(
        "cp.async.bulk.global.shared::cta.bulk_group [%0], [%1], %2;"
        :: "l"(dst_gmem), "r"(src_smem), "r"(bytes) : "memory");
}

__global__ __launch_bounds__(THREADS, 1) void widthap_kernel(
    const float* __restrict__ x,
    const float* __restrict__ att,
    float* __restrict__ out)
{
    extern __shared__ char smem[];
    const int tid = threadIdx.x;
    const int b   = blockIdx.y;
    const int t0  = blockIdx.x * TT;

    uint32_t sbase = smem_u32(smem);
    uint32_t mbar  = sbase + MBAR_OFF;      // 4 x 8B

    float* wa = reinterpret_cast<float*>(smem + WA_OFF);

    // weights for tile-relative rows 0..67
    if (tid < TT + 4) // 68
        wa[tid] = att[b * PAD + t0 + tid];

    if (tid == 0) {
        #pragma unroll
        for (int s = 0; s < IN_STAGES; s++)
            mbar_init(mbar + s * 8, 1);
    }
    __syncthreads();

    const char* xsrc = reinterpret_cast<const char*>(x) +
                       ((size_t)b * PAD + t0) * ROWB;
    char* odst = reinterpret_cast<char*>(out) +
                 ((size_t)b * LENGTH + t0) * ROWB;

    // prime pipeline: input chunks 0..2
    if (tid == 0) {
        #pragma unroll
        for (int ci = 0; ci < 3; ci++) {
            uint32_t bytes = CHUNK;          // ci<8 always full here
            mbar_expect_tx(mbar + (ci & 3) * 8, bytes);
            bulk_g2s(sbase + IN_OFF + (ci & 3) * CHUNK,
                     xsrc + (size_t)ci * CHUNK, bytes, mbar + (ci & 3) * 8);
        }
    }

    const int h4   = tid % (H / 4);          // 0..191 (float4 column)
    const int half = tid / (H / 4);          // 0 or 1 (rows 0-3 vs 4-7)

    for (int co = 0; co < NCH; co++) {
        if (tid == 0) {
            if (co >= 2) {
                // out stage co%2 reusable once store co-2 has read smem
                asm volatile("cp.async.bulk.wait_group.read 1;" ::: "memory");
            }
            int ci = co + 3;
            if (ci < NIN) {
                uint32_t bytes = (ci == NIN - 1) ? (4 * ROWB) : CHUNK;
                mbar_expect_tx(mbar + (ci & 3) * 8, bytes);
                bulk_g2s(sbase + IN_OFF + (ci & 3) * CHUNK,
                         xsrc + (size_t)ci * CHUNK, bytes, mbar + (ci & 3) * 8);
            }
        }
        __syncthreads();   // out-stage freedom visible to all

        // need input chunks co and co+1
        mbar_wait(mbar + (co & 3) * 8, (co >> 2) & 1);
        mbar_wait(mbar + ((co + 1) & 3) * 8, ((co + 1) >> 2) & 1);

        // compute output rows Rbase..Rbase+3 (tile-relative)
        const int Rbase = co * CR + half * 4;

        float4 w[8];
        #pragma unroll
        for (int k = 0; k < 8; k++) {
            int R = Rbase + k;
            const float4* p = reinterpret_cast<const float4*>(
                smem + IN_OFF + ((R >> 3) & 3) * CHUNK + (R & 7) * ROWB) + h4;
            float4 v = *p;
            float  a = wa[R];
            w[k] = make_float4(v.x * a, v.y * a, v.z * a, v.w * a);
        }

        float4* outstage = reinterpret_cast<float4*>(
            smem + OUT_OFF + (co & 1) * CHUNK);
        #pragma unroll
        for (int r = 0; r < 4; r++) {
            float4 s;
            s.x = w[r].x + w[r+1].x + w[r+2].x + w[r+3].x + w[r+4].x;
            s.y = w[r].y + w[r+1].y + w[r+2].y + w[r+3].y + w[r+4].y;
            s.z = w[r].z + w[r+1].z + w[r+2].z + w[r+3].z + w[r+4].z;
            s.w = w[r].w + w[r+1].w + w[r+2].w + w[r+3].w + w[r+4].w;
            outstage[(half * 4 + r) * (H / 4) + h4] = s;
        }

        __syncthreads();   // all STS of this out chunk done

        if (tid == 0) {
            asm volatile("fence.proxy.async.shared::cta;" ::: "memory");
            bulk_s2g(odst + (size_t)co * CHUNK,
                     sbase + OUT_OFF + (co & 1) * CHUNK, CHUNK);
            asm volatile("cp.async.bulk.commit_group;" ::: "memory");
        }
    }

    if (tid == 0)
        asm volatile("cp.async.bulk.wait_group.read 0;" ::: "memory");
}

extern "C" void kernel_launch(void* const* d_in, const int* in_sizes, int n_in,
                              void* d_out, int out_size)
{
    const float* x   = (const float*)d_in[0];   // (32,1,2052,768)
    const float* att = (const float*)d_in[1];   // (32,2052)
    float* out       = (float*)d_out;           // (32,1,2048,768)

    cudaFuncSetAttribute(widthap_kernel,
                         cudaFuncAttributeMaxDynamicSharedMemorySize, SMEM_TOTAL);

    dim3 grid(LENGTH / TT, B);   // (32, 32) = 1024 CTAs
    dim3 block(THREADS);         // 384
    widthap_kernel<<<grid, block, SMEM_TOTAL>>>(x, att, out);
}

// round 4
// speedup vs baseline: 1.4724x; 1.0092x over previous
#include <cuda_runtime.h>
#include <cstdint>

// out[b, t, h] = sum_{j=0..4} x[b, t+j, h] * a[b, t+j]
// x: (32,1,2052,768) f32, a: (32,2052) f32, out: (32,1,2048,768) f32
//
// R4: cp.async.bulk pipeline, resized for 2 CTAs/SM.
//   CR=4 rows (12KB chunks), 6-stage input ring, 3-stage output ring
//   => 111KB smem/CTA => occupancy 2. One CTA's compute/barrier phases
//   overlap the other's bulk DMA, keeping the MC fed continuously.

constexpr int LENGTH = 2048;
constexpr int H      = 768;
constexpr int PAD    = LENGTH + 4;           // 2052
constexpr int ROWB   = H * 4;                // 3072 B per row
constexpr int TT     = 64;                   // output rows per CTA
constexpr int CR     = 4;                    // rows per chunk
constexpr int CHUNK  = CR * ROWB;            // 12288 B
constexpr int NCH    = TT / CR;              // 16 output chunks
constexpr int NIN    = NCH + 1;              // 17 input chunks (68 rows exactly)
constexpr int IN_STAGES  = 6;
constexpr int OUT_STAGES = 3;
constexpr int PRIME  = 5;
constexpr int B      = 32;
constexpr int THREADS = 384;

constexpr int MBAR_OFF = 0;                              // 6 mbarriers * 8B
constexpr int WA_OFF   = 64;                             // 68 floats
constexpr int IN_OFF   = 512;
constexpr int OUT_OFF  = IN_OFF + IN_STAGES * CHUNK;     // 74240
constexpr int SMEM_TOTAL = OUT_OFF + OUT_STAGES * CHUNK; // 111104

__device__ __forceinline__ uint32_t smem_u32(const void* p) {
    return (uint32_t)__cvta_generic_to_shared(p);
}

__device__ __forceinline__ void mbar_init(uint32_t bar, uint32_t count) {
    asm volatile("mbarrier.init.shared.b64 [%0], %1;" :: "r"(bar), "r"(count) : "memory");
}

__device__ __forceinline__ void mbar_expect_tx(uint32_t bar, uint32_t bytes) {
    asm volatile("mbarrier.arrive.expect_tx.shared.b64 _, [%0], %1;"
                 :: "r"(bar), "r"(bytes) : "memory");
}

__device__ __forceinline__ void mbar_wait(uint32_t bar, uint32_t parity) {
    uint32_t done;
    asm volatile(
        "{\n\t.reg .pred p;\n\t"
        "mbarrier.try_wait.parity.acquire.cta.shared::cta.b64 p, [%1], %2;\n\t"
        "selp.b32 %0, 1, 0, p;\n\t}"
        : "=r"(done) : "r"(bar), "r"(parity) : "memory");
    if (!done) {
        asm volatile(
            "{\n\t.reg .pred P1;\n\t"
            "W_%=:\n\t"
            "mbarrier.try_wait.parity.acquire.cta.shared::cta.b64 P1, [%0], %1, 0x989680;\n\t"
            "@P1 bra.uni D_%=;\n\t"
            "bra.uni W_%=;\n\t"
            "D_%=:\n\t}"
            :: "r"(bar), "r"(parity) : "memory");
    }
}

__device__ __forceinline__ void bulk_g2s(uint32_t dst_smem, const void* src_gmem,
                                         uint32_t bytes, uint32_t bar) {
    asm volatile(
        "cp.async.bulk.shared::cluster.global.mbarrier::complete_tx::bytes "
        "[%0], [%1], %2, [%3];"
        :: "r"(dst_smem), "l"(src_gmem), "r"(bytes), "r"(bar) : "memory");
}

__device__ __forceinline__ void bulk_s2g(void* dst_gmem, uint32_t src_smem,
                                         uint32_t bytes) {
    asm volatile(
        "cp.async.bulk.global.shared::cta.bulk_group [%0], [%1], %2;"
        :: "l"(dst_gmem), "r"(src_smem), "r"(bytes) : "memory");
}

__global__ __launch_bounds__(THREADS, 2) void widthap_kernel(
    const float* __restrict__ x,
    const float* __restrict__ att,
    float* __restrict__ out)
{
    extern __shared__ char smem[];
    const int tid = threadIdx.x;
    const int b   = blockIdx.y;
    const int t0  = blockIdx.x * TT;

    uint32_t sbase = smem_u32(smem);
    uint32_t mbar  = sbase + MBAR_OFF;

    float* wa = reinterpret_cast<float*>(smem + WA_OFF);
    if (tid < TT + 4)   // 68 weights
        wa[tid] = att[b * PAD + t0 + tid];

    if (tid == 0) {
        #pragma unroll
        for (int s = 0; s < IN_STAGES; s++)
            mbar_init(mbar + s * 8, 1);
    }
    __syncthreads();

    const char* xsrc = reinterpret_cast<const char*>(x) +
                       ((size_t)b * PAD + t0) * ROWB;
    char* odst = reinterpret_cast<char*>(out) +
                 ((size_t)b * LENGTH + t0) * ROWB;

    // prime input chunks 0..PRIME-1
    if (tid == 0) {
        #pragma unroll
        for (int ci = 0; ci < PRIME; ci++) {
            mbar_expect_tx(mbar + ci * 8, CHUNK);
            bulk_g2s(sbase + IN_OFF + ci * CHUNK,
                     xsrc + (size_t)ci * CHUNK, CHUNK, mbar + ci * 8);
        }
    }

    const int h4   = tid % (H / 4);          // 0..191
    const int half = tid / (H / 4);          // 0 or 1

    for (int co = 0; co < NCH; co++) {
        if (tid == 0) {
            if (co >= OUT_STAGES)
                asm volatile("cp.async.bulk.wait_group.read 2;" ::: "memory");
            int ci = co + PRIME;
            if (ci < NIN) {
                int s = ci % IN_STAGES;
                mbar_expect_tx(mbar + s * 8, CHUNK);
                bulk_g2s(sbase + IN_OFF + s * CHUNK,
                         xsrc + (size_t)ci * CHUNK, CHUNK, mbar + s * 8);
            }
        }
        __syncthreads();

        // compute chunk co needs input chunks co and co+1
        mbar_wait(mbar + (co % IN_STAGES) * 8, (co / IN_STAGES) & 1);
        mbar_wait(mbar + ((co + 1) % IN_STAGES) * 8, ((co + 1) / IN_STAGES) & 1);

        const int Rbase = co * CR + half * 2;   // this thread's first output row

        float4 w[6];
        #pragma unroll
        for (int k = 0; k < 6; k++) {
            int R = Rbase + k;                  // tile-relative input row
            const float4* p = reinterpret_cast<const float4*>(
                smem + IN_OFF + ((R >> 2) % IN_STAGES) * CHUNK + (R & 3) * ROWB) + h4;
            float4 v = *p;
            float  a = wa[R];
            w[k] = make_float4(v.x * a, v.y * a, v.z * a, v.w * a);
        }

        float4* outstage = reinterpret_cast<float4*>(
            smem + OUT_OFF + (co % OUT_STAGES) * CHUNK);
        #pragma unroll
        for (int r = 0; r < 2; r++) {
            float4 s;
            s.x = w[r].x + w[r+1].x + w[r+2].x + w[r+3].x + w[r+4].x;
            s.y = w[r].y + w[r+1].y + w[r+2].y + w[r+3].y + w[r+4].y;
            s.z = w[r].z + w[r+1].z + w[r+2].z + w[r+3].z + w[r+4].z;
            s.w = w[r].w + w[r+1].w + w[r+2].w + w[r+3].w + w[r+4].w;
            outstage[(half * 2 + r) * (H / 4) + h4] = s;
        }

        __syncthreads();

        if (tid == 0) {
            asm volatile("fence.proxy.async.shared::cta;" ::: "memory");
            bulk_s2g(odst + (size_t)co * CHUNK,
                     sbase + OUT_OFF + (co % OUT_STAGES) * CHUNK, CHUNK);
            asm volatile("cp.async.bulk.commit_group;" ::: "memory");
        }
    }

    if (tid == 0)
        asm volatile("cp.async.bulk.wait_group.read 0;" ::: "memory");
}

extern "C" void kernel_launch(void* const* d_in, const int* in_sizes, int n_in,
                              void* d_out, int out_size)
{
    const float* x   = (const float*)d_in[0];   // (32,1,2052,768)
    const float* att = (const float*)d_in[1];   // (32,2052)
    float* out       = (float*)d_out;           // (32,1,2048,768)

    cudaFuncSetAttribute(widthap_kernel,
                         cudaFuncAttributeMaxDynamicSharedMemorySize, SMEM_TOTAL);

    dim3 grid(LENGTH / TT, B);   // (32, 32) = 1024 CTAs
    dim3 block(THREADS);
    widthap_kernel<<<grid, block, SMEM_TOTAL>>>(x, att, out);
}

// round 5
// speedup vs baseline: 1.5128x; 1.0274x over previous
#include <cuda_runtime.h>
#include <cstdint>

// out[b, t, h] = sum_{j=0..4} x[b, t+j, h] * a[b, t+j]
// x: (32,1,2052,768) f32, a: (32,2052) f32, out: (32,1,2048,768) f32
//
// R5: bulk-DMA pipeline + column-persistent register sliding window.
//   192 threads/CTA, each owns one float4 column; 4-row (12KB) chunks.
//   Each smem input byte is LDS-read exactly once; one __syncthreads and
//   one mbar-wait per chunk. 4-stage input ring, 3-stage output ring.

constexpr int LENGTH = 2048;
constexpr int H      = 768;
constexpr int PAD    = LENGTH + 4;           // 2052
constexpr int ROWB   = H * 4;                // 3072 B per row
constexpr int H4     = H / 4;                // 192
constexpr int TT     = 64;                   // output rows per CTA
constexpr int CR     = 4;                    // rows per chunk
constexpr int CHUNK  = CR * ROWB;            // 12288 B
constexpr int NCH    = TT / CR;              // 16 output chunks
constexpr int NIN    = NCH + 1;              // 17 input chunks (68 rows)
constexpr int IN_STAGES  = 4;
constexpr int OUT_STAGES = 3;
constexpr int B      = 32;
constexpr int THREADS = H4;                  // 192

constexpr int MBAR_OFF = 0;                              // 4 mbarriers * 8B
constexpr int WA_OFF   = 64;                             // 68 floats
constexpr int IN_OFF   = 512;
constexpr int OUT_OFF  = IN_OFF + IN_STAGES * CHUNK;     // 49664
constexpr int SMEM_TOTAL = OUT_OFF + OUT_STAGES * CHUNK; // 86528

__device__ __forceinline__ uint32_t smem_u32(const void* p) {
    return (uint32_t)__cvta_generic_to_shared(p);
}
__device__ __forceinline__ void mbar_init(uint32_t bar, uint32_t count) {
    asm volatile("mbarrier.init.shared.b64 [%0], %1;" :: "r"(bar), "r"(count) : "memory");
}
__device__ __forceinline__ void mbar_expect_tx(uint32_t bar, uint32_t bytes) {
    asm volatile("mbarrier.arrive.expect_tx.shared.b64 _, [%0], %1;"
                 :: "r"(bar), "r"(bytes) : "memory");
}
__device__ __forceinline__ void mbar_wait(uint32_t bar, uint32_t parity) {
    uint32_t done;
    asm volatile(
        "{\n\t.reg .pred p;\n\t"
        "mbarrier.try_wait.parity.acquire.cta.shared::cta.b64 p, [%1], %2;\n\t"
        "selp.b32 %0, 1, 0, p;\n\t}"
        : "=r"(done) : "r"(bar), "r"(parity) : "memory");
    if (!done) {
        asm volatile(
            "{\n\t.reg .pred P1;\n\t"
            "W_%=:\n\t"
            "mbarrier.try_wait.parity.acquire.cta.shared::cta.b64 P1, [%0], %1, 0x989680;\n\t"
            "@P1 bra.uni D_%=;\n\t"
            "bra.uni W_%=;\n\t"
            "D_%=:\n\t}"
            :: "r"(bar), "r"(parity) : "memory");
    }
}
__device__ __forceinline__ void bulk_g2s(uint32_t dst_smem, const void* src_gmem,
                                         uint32_t bytes, uint32_t bar) {
    asm volatile(
        "cp.async.bulk.shared::cluster.global.mbarrier::complete_tx::bytes "
        "[%0], [%1], %2, [%3];"
        :: "r"(dst_smem), "l"(src_gmem), "r"(bytes), "r"(bar) : "memory");
}
__device__ __forceinline__ void bulk_s2g(void* dst_gmem, uint32_t src_smem,
                                         uint32_t bytes) {
    asm volatile(
        "cp.async.bulk.global.shared::cta.bulk_group [%0], [%1], %2;"
        :: "l"(dst_gmem), "r"(src_smem), "r"(bytes) : "memory");
}

__global__ __launch_bounds__(THREADS, 2) void widthap_kernel(
    const float* __restrict__ x,
    const float* __restrict__ att,
    float* __restrict__ out)
{
    extern __shared__ char smem[];
    const int tid = threadIdx.x;     // 0..191 = float4 column
    const int b   = blockIdx.y;
    const int t0  = blockIdx.x * TT;

    uint32_t sbase = smem_u32(smem);
    uint32_t mbar  = sbase + MBAR_OFF;

    float* wa = reinterpret_cast<float*>(smem + WA_OFF);
    if (tid < TT + 4)   // 68 weights
        wa[tid] = att[b * PAD + t0 + tid];

    if (tid == 0) {
        #pragma unroll
        for (int s = 0; s < IN_STAGES; s++)
            mbar_init(mbar + s * 8, 1);
    }
    __syncthreads();

    const char* xsrc = reinterpret_cast<const char*>(x) +
                       ((size_t)b * PAD + t0) * ROWB;
    char* odst = reinterpret_cast<char*>(out) +
                 ((size_t)b * LENGTH + t0) * ROWB;

    // prime input chunks 0..3 into stages 0..3
    if (tid == 0) {
        #pragma unroll
        for (int ci = 0; ci < IN_STAGES; ci++) {
            mbar_expect_tx(mbar + ci * 8, CHUNK);
            bulk_g2s(sbase + IN_OFF + ci * CHUNK,
                     xsrc + (size_t)ci * CHUNK, CHUNK, mbar + ci * 8);
        }
    }

    // Prologue: consume chunk 0 into the register window (rows 0..3, weighted)
    float4 w0, w1, w2, w3;
    {
        mbar_wait(mbar + 0, 0);
        const float4* in0 = reinterpret_cast<const float4*>(smem + IN_OFF);
        float4 v;
        v = in0[0 * H4 + tid]; w0 = make_float4(v.x*wa[0], v.y*wa[0], v.z*wa[0], v.w*wa[0]);
        v = in0[1 * H4 + tid]; w1 = make_float4(v.x*wa[1], v.y*wa[1], v.z*wa[1], v.w*wa[1]);
        v = in0[2 * H4 + tid]; w2 = make_float4(v.x*wa[2], v.y*wa[2], v.z*wa[2], v.w*wa[2]);
        v = in0[3 * H4 + tid]; w3 = make_float4(v.x*wa[3], v.y*wa[3], v.z*wa[3], v.w*wa[3]);
    }

    for (int co = 0; co < NCH; co++) {
        // (a) free the oldest out-stage before anyone STS-reuses it
        if (tid == 0 && co >= 2)
            asm volatile("cp.async.bulk.wait_group.read 1;" ::: "memory");

        // (b) one barrier: prev iter's LDS+STS done; out-stage drain visible
        __syncthreads();

        // (c) tid0: store prev output chunk; refill the input stage freed in (b)
        if (tid == 0) {
            if (co >= 1) {
                asm volatile("fence.proxy.async.shared::cta;" ::: "memory");
                bulk_s2g(odst + (size_t)(co - 1) * CHUNK,
                         sbase + OUT_OFF + ((co - 1) % OUT_STAGES) * CHUNK, CHUNK);
                asm volatile("cp.async.bulk.commit_group;" ::: "memory");
            }
            int ci = co + IN_STAGES;        // next chunk into stage co%4
            if (ci < NIN) {
                int s = ci % IN_STAGES;
                mbar_expect_tx(mbar + s * 8, CHUNK);
                bulk_g2s(sbase + IN_OFF + s * CHUNK,
                         xsrc + (size_t)ci * CHUNK, CHUNK, mbar + s * 8);
            }
        }

        // (d) consume input chunk co+1 (single read of each smem byte)
        const int ci = co + 1;
        mbar_wait(mbar + (ci % IN_STAGES) * 8, (ci / IN_STAGES) & 1);

        const float4* in = reinterpret_cast<const float4*>(
            smem + IN_OFF + (ci % IN_STAGES) * CHUNK);
        const int wb = 4 * co + 4;   // weight index of first new row
        float4 n0, n1, n2, n3, v;
        v = in[0 * H4 + tid]; { float a = wa[wb+0]; n0 = make_float4(v.x*a, v.y*a, v.z*a, v.w*a); }
        v = in[1 * H4 + tid]; { float a = wa[wb+1]; n1 = make_float4(v.x*a, v.y*a, v.z*a, v.w*a); }
        v = in[2 * H4 + tid]; { float a = wa[wb+2]; n2 = make_float4(v.x*a, v.y*a, v.z*a, v.w*a); }
        v = in[3 * H4 + tid]; { float a = wa[wb+3]; n3 = make_float4(v.x*a, v.y*a, v.z*a, v.w*a); }

        float4* os = reinterpret_cast<float4*>(
            smem + OUT_OFF + (co % OUT_STAGES) * CHUNK);
        float4 s;
        // out row 0: w0+w1+w2+w3+n0
        s.x = w0.x+w1.x+w2.x+w3.x+n0.x; s.y = w0.y+w1.y+w2.y+w3.y+n0.y;
        s.z = w0.z+w1.z+w2.z+w3.z+n0.z; s.w = w0.w+w1.w+w2.w+w3.w+n0.w;
        os[0 * H4 + tid] = s;
        // out row 1: w1+w2+w3+n0+n1
        s.x = w1.x+w2.x+w3.x+n0.x+n1.x; s.y = w1.y+w2.y+w3.y+n0.y+n1.y;
        s.z = w1.z+w2.z+w3.z+n0.z+n1.z; s.w = w1.w+w2.w+w3.w+n0.w+n1.w;
        os[1 * H4 + tid] = s;
        // out row 2: w2+w3+n0+n1+n2
        s.x = w2.x+w3.x+n0.x+n1.x+n2.x; s.y = w2.y+w3.y+n0.y+n1.y+n2.y;
        s.z = w2.z+w3.z+n0.z+n1.z+n2.z; s.w = w2.w+w3.w+n0.w+n1.w+n2.w;
        os[2 * H4 + tid] = s;
        // out row 3: w3+n0+n1+n2+n3
        s.x = w3.x+n0.x+n1.x+n2.x+n3.x; s.y = w3.y+n0.y+n1.y+n2.y+n3.y;
        s.z = w3.z+n0.z+n1.z+n2.z+n3.z; s.w = w3.w+n0.w+n1.w+n2.w+n3.w;
        os[3 * H4 + tid] = s;

        w0 = n0; w1 = n1; w2 = n2; w3 = n3;
    }

    // Epilogue: store last output chunk
    __syncthreads();
    if (tid == 0) {
        asm volatile("fence.proxy.async.shared::cta;" ::: "memory");
        bulk_s2g(odst + (size_t)(NCH - 1) * CHUNK,
                 sbase + OUT_OFF + ((NCH - 1) % OUT_STAGES) * CHUNK, CHUNK);
        asm volatile("cp.async.bulk.commit_group;" ::: "memory");
        asm volatile("cp.async.bulk.wait_group.read 0;" ::: "memory");
    }
}

extern "C" void kernel_launch(void* const* d_in, const int* in_sizes, int n_in,
                              void* d_out, int out_size)
{
    const float* x   = (const float*)d_in[0];   // (32,1,2052,768)
    const float* att = (const float*)d_in[1];   // (32,2052)
    float* out       = (float*)d_out;           // (32,1,2048,768)

    cudaFuncSetAttribute(widthap_kernel,
                         cudaFuncAttributeMaxDynamicSharedMemorySize, SMEM_TOTAL);

    dim3 grid(LENGTH / TT, B);   // (32, 32) = 1024 CTAs
    dim3 block(THREADS);         // 192
    widthap_kernel<<<grid, block, SMEM_TOTAL>>>(x, att, out);
}